// round 2
// baseline (speedup 1.0000x reference)
#include <cuda_runtime.h>
#include <math.h>

// ---------------- problem constants ----------------
#define NN 10000
#define DD 256
#define EE 320000
#define MAXNORM 0.996f          // (1 - 4e-3)/sqrt(c), c=1
#define MINNORM 1e-15f
#define ATANH_CLIP (1.0f - 1e-7f)

// ---------------- scratch (static device globals; no allocation) ----------
__device__ float g_h  [NN * DD];
__device__ float g_mx [NN * DD];
__device__ float g_xt [NN * DD];
__device__ float g_agg[NN * DD];
__device__ float g_bias[DD];
__device__ float g_biasy2;

// ---------------- numerics (flag-independent accurate tanh/atanh) ---------
__device__ __forceinline__ float tanh_acc(float x) {
    float a = fabsf(x);
    if (a > 15.f) return copysignf(1.f, x);
    float s = expm1f(2.f * a);          // accurate for small a, exact at 0
    float r = s / (s + 2.f);            // 1 - tanh preserved to ~1e-6 rel
    return copysignf(r, x);
}
__device__ __forceinline__ float atanh_clip(float r) {
    // r >= 0 here (norms). clip matches jnp.clip(x, ..., 1-1e-7)
    float a = fminf(r, ATANH_CLIP);
    return 0.5f * log1pf(2.f * a / (1.f - a));
}

// ---------------- small float4 helpers ----------------
__device__ __forceinline__ float d4(float4 v)  { return v.x*v.x + v.y*v.y + v.z*v.z + v.w*v.w; }
__device__ __forceinline__ float dd4(float4 a, float4 b) { return a.x*b.x + a.y*b.y + a.z*b.z + a.w*b.w; }
__device__ __forceinline__ float4 s4(float4 v, float s) { return make_float4(v.x*s, v.y*s, v.z*s, v.w*s); }

__device__ __forceinline__ float wredsum(float v) {
    #pragma unroll
    for (int o = 16; o; o >>= 1) v += __shfl_xor_sync(0xffffffffu, v, o);
    return v;
}

// row-norm of (a0,a1) across the warp (each lane holds 8 elems as 2 float4)
__device__ __forceinline__ float rownorm(float4 a0, float4 a1) {
    return fmaxf(sqrtf(wredsum(d4(a0) + d4(a1))), MINNORM);
}

// ---------------- stage A: h = proj(expmap0(x)) ----------------
__global__ void k_init(const float* __restrict__ x) {
    int w = threadIdx.x >> 5, lane = threadIdx.x & 31;
    int row = blockIdx.x * 8 + w;
    if (row >= NN) return;
    const float4* xp = (const float4*)x + (size_t)row * 64;
    float4 v0 = xp[lane], v1 = xp[lane + 32];
    float n = rownorm(v0, v1);
    float s = tanh_acc(n) / n;
    float4 e0 = s4(v0, s), e1 = s4(v1, s);
    float n2 = rownorm(e0, e1);
    if (n2 > MAXNORM) { float f = MAXNORM / n2; e0 = s4(e0, f); e1 = s4(e1, f); }
    float4* hp = (float4*)g_h + (size_t)row * 64;
    hp[lane] = e0; hp[lane + 32] = e1;
}

// ---------------- bias: hyp_bias = proj(expmap0(b)), plus |bias|^2 --------
__global__ void k_bias(const float* __restrict__ b) {
    int lane = threadIdx.x;   // 32 threads, 1 warp
    const float4* bp = (const float4*)b;
    float4 v0 = bp[lane], v1 = bp[lane + 32];
    float n = rownorm(v0, v1);
    float s = tanh_acc(n) / n;
    v0 = s4(v0, s); v1 = s4(v1, s);
    float n2 = rownorm(v0, v1);
    if (n2 > MAXNORM) { float f = MAXNORM / n2; v0 = s4(v0, f); v1 = s4(v1, f); }
    float y2 = wredsum(d4(v0) + d4(v1));
    ((float4*)g_bias)[lane] = v0;
    ((float4*)g_bias)[lane + 32] = v1;
    if (lane == 0) g_biasy2 = y2;
}

// ---------------- GEMM: g_mx = g_h @ W^T  (M=NN, N=K=256) ----------------
// A = g_h [M,256] row-major, B = W [256,256] row-major; C[i][j]=sum_k A[i][k]B[j][k]
__global__ __launch_bounds__(256) void k_gemm(const float* __restrict__ Bm) {
    __shared__ float As[32][64];
    __shared__ float Bs[32][64];
    int tid = threadIdx.x;
    int tx = tid & 15, ty = tid >> 4;
    int m0 = blockIdx.y * 64;
    int n0 = blockIdx.x * 64;
    float acc[4][4];
    #pragma unroll
    for (int i = 0; i < 4; i++)
        #pragma unroll
        for (int j = 0; j < 4; j++) acc[i][j] = 0.f;

    for (int k0 = 0; k0 < 256; k0 += 32) {
        #pragma unroll
        for (int l = 0; l < 2; l++) {
            int idx = tid + 256 * l;      // 0..511, coalesced
            int r = idx >> 3, c4 = idx & 7;
            float4 a = make_float4(0.f, 0.f, 0.f, 0.f);
            if (m0 + r < NN)
                a = *(const float4*)(g_h + (size_t)(m0 + r) * 256 + k0 + c4 * 4);
            As[c4*4+0][r] = a.x; As[c4*4+1][r] = a.y; As[c4*4+2][r] = a.z; As[c4*4+3][r] = a.w;
            float4 b = *(const float4*)(Bm + (size_t)(n0 + r) * 256 + k0 + c4 * 4);
            Bs[c4*4+0][r] = b.x; Bs[c4*4+1][r] = b.y; Bs[c4*4+2][r] = b.z; Bs[c4*4+3][r] = b.w;
        }
        __syncthreads();
        #pragma unroll
        for (int kk = 0; kk < 32; kk++) {
            float4 av = *(const float4*)&As[kk][ty * 4];
            float4 bv = *(const float4*)&Bs[kk][tx * 4];
            float ar[4] = {av.x, av.y, av.z, av.w};
            float br[4] = {bv.x, bv.y, bv.z, bv.w};
            #pragma unroll
            for (int i = 0; i < 4; i++)
                #pragma unroll
                for (int j = 0; j < 4; j++) acc[i][j] += ar[i] * br[j];
        }
        __syncthreads();
    }
    #pragma unroll
    for (int i = 0; i < 4; i++) {
        int m = m0 + ty * 4 + i;
        if (m < NN) {
            float4 v = make_float4(acc[i][0], acc[i][1], acc[i][2], acc[i][3]);
            *(float4*)(g_mx + (size_t)m * 256 + n0 + tx * 4) = v;
        }
    }
}

// ---------------- fused HypLinear tail + logmap0, also zeroes agg --------
// xt = logmap0( proj( mobius_add( proj(mobius_matvec_result), hyp_bias ) ) )
__global__ void k_pre() {
    int w = threadIdx.x >> 5, lane = threadIdx.x & 31;
    int row = blockIdx.x * 8 + w;
    if (row >= NN) return;
    const float4* hp = (const float4*)g_h  + (size_t)row * 64;
    const float4* mp = (const float4*)g_mx + (size_t)row * 64;
    float4 h0 = hp[lane], h1 = hp[lane + 32];
    float4 m0 = mp[lane], m1 = mp[lane + 32];

    // mobius_matvec
    float xn  = rownorm(h0, h1);
    float mn2 = wredsum(d4(m0) + d4(m1));
    bool  zero = (mn2 == 0.f);
    float mxn = fmaxf(sqrtf(mn2), MINNORM);
    float arg = mxn / xn * atanh_clip(xn);
    float sc  = tanh_acc(arg) / mxn;
    if (zero) sc = 0.f;
    float4 r0 = s4(m0, sc), r1 = s4(m1, sc);
    // proj
    float rn = rownorm(r0, r1);
    if (rn > MAXNORM) { float f = MAXNORM / rn; r0 = s4(r0, f); r1 = s4(r1, f); }

    // mobius_add with hyp_bias
    float4 b0 = ((const float4*)g_bias)[lane];
    float4 b1 = ((const float4*)g_bias)[lane + 32];
    float x2 = wredsum(d4(r0) + d4(r1));
    float xy = wredsum(dd4(r0, b0) + dd4(r1, b1));
    float y2 = g_biasy2;
    float ca = 1.f + 2.f * xy + y2;
    float cb = 1.f - x2;
    float den = fmaxf(1.f + 2.f * xy + x2 * y2, MINNORM);
    float4 q0, q1;
    q0.x = (ca*r0.x + cb*b0.x)/den; q0.y = (ca*r0.y + cb*b0.y)/den;
    q0.z = (ca*r0.z + cb*b0.z)/den; q0.w = (ca*r0.w + cb*b0.w)/den;
    q1.x = (ca*r1.x + cb*b1.x)/den; q1.y = (ca*r1.y + cb*b1.y)/den;
    q1.z = (ca*r1.z + cb*b1.z)/den; q1.w = (ca*r1.w + cb*b1.w)/den;
    // proj
    float qn = rownorm(q0, q1);
    if (qn > MAXNORM) { float f = MAXNORM / qn; q0 = s4(q0, f); q1 = s4(q1, f); }

    // logmap0
    float pn = rownorm(q0, q1);
    float ls = atanh_clip(pn) / pn;
    q0 = s4(q0, ls); q1 = s4(q1, ls);

    float4* xp = (float4*)g_xt + (size_t)row * 64;
    xp[lane] = q0; xp[lane + 32] = q1;
    // zero the aggregation buffer for the upcoming scatter
    float4* ap = (float4*)g_agg + (size_t)row * 64;
    float4 z = make_float4(0.f, 0.f, 0.f, 0.f);
    ap[lane] = z; ap[lane + 32] = z;
}

// ---------------- edge aggregation: agg[dst] += w * xt[src] ---------------
// one warp per edge, grid-stride; both gathers issued before the REDs (MLP=2)
__global__ __launch_bounds__(256) void k_agg(const float* __restrict__ ew,
                                             const int* __restrict__ esrc,
                                             const int* __restrict__ edst) {
    int warpsPerGrid = (int)((gridDim.x * blockDim.x) >> 5);
    int gw0 = (int)((blockIdx.x * blockDim.x + threadIdx.x) >> 5);
    int lane = threadIdx.x & 31;
    for (int gw = gw0; gw < EE; gw += warpsPerGrid) {
        int s = __ldg(&esrc[gw]);
        int d = __ldg(&edst[gw]);
        float w = __ldg(&ew[gw]);
        const float4* xp = (const float4*)g_xt + (size_t)s * 64;
        float4 v0 = __ldg(&xp[lane]);
        float4 v1 = __ldg(&xp[lane + 32]);
        v0 = s4(v0, w); v1 = s4(v1, w);
        float* ap = g_agg + (size_t)d * 256;
        float* a0 = ap + (size_t)lane * 4;
        float* a1 = ap + (size_t)(lane + 32) * 4;
        asm volatile("red.global.add.v4.f32 [%0], {%1,%2,%3,%4};"
                     :: "l"(a0), "f"(v0.x), "f"(v0.y), "f"(v0.z), "f"(v0.w)
                     : "memory");
        asm volatile("red.global.add.v4.f32 [%0], {%1,%2,%3,%4};"
                     :: "l"(a1), "f"(v1.x), "f"(v1.y), "f"(v1.z), "f"(v1.w)
                     : "memory");
    }
}

// ---------------- post-agg: h = proj(expmap0( relu(logmap0( proj(expmap0(agg)) )) ))
__global__ void k_post(float* __restrict__ out, int write_out) {
    int w = threadIdx.x >> 5, lane = threadIdx.x & 31;
    int row = blockIdx.x * 8 + w;
    if (row >= NN) return;
    const float4* ap = (const float4*)g_agg + (size_t)row * 64;
    float4 a0 = ap[lane], a1 = ap[lane + 32];

    // expmap0
    float n1 = rownorm(a0, a1);
    float s = tanh_acc(n1) / n1;
    float4 e0 = s4(a0, s), e1 = s4(a1, s);
    // proj
    float n2 = rownorm(e0, e1);
    if (n2 > MAXNORM) { float f = MAXNORM / n2; e0 = s4(e0, f); e1 = s4(e1, f); }
    // logmap0 + relu
    float pn = rownorm(e0, e1);
    float ls = atanh_clip(pn) / pn;
    float4 u0, u1;
    u0.x = fmaxf(e0.x * ls, 0.f); u0.y = fmaxf(e0.y * ls, 0.f);
    u0.z = fmaxf(e0.z * ls, 0.f); u0.w = fmaxf(e0.w * ls, 0.f);
    u1.x = fmaxf(e1.x * ls, 0.f); u1.y = fmaxf(e1.y * ls, 0.f);
    u1.z = fmaxf(e1.z * ls, 0.f); u1.w = fmaxf(e1.w * ls, 0.f);
    // expmap0
    float un = rownorm(u0, u1);
    float s2 = tanh_acc(un) / un;
    float4 o0 = s4(u0, s2), o1 = s4(u1, s2);
    // proj
    float n3 = rownorm(o0, o1);
    if (n3 > MAXNORM) { float f = MAXNORM / n3; o0 = s4(o0, f); o1 = s4(o1, f); }

    float4* dst = write_out ? ((float4*)out + (size_t)row * 64)
                            : ((float4*)g_h + (size_t)row * 64);
    dst[lane] = o0; dst[lane + 32] = o1;
}

// ---------------- launch ----------------
extern "C" void kernel_launch(void* const* d_in, const int* in_sizes, int n_in,
                              void* d_out, int out_size) {
    const float* x    = (const float*)d_in[0];
    const float* W1   = (const float*)d_in[1];
    const float* b1   = (const float*)d_in[2];
    const float* W2   = (const float*)d_in[3];
    const float* b2   = (const float*)d_in[4];
    const float* ew   = (const float*)d_in[5];
    const int*   esrc = (const int*)d_in[6];
    const int*   edst = (const int*)d_in[7];
    float* out = (float*)d_out;
    (void)in_sizes; (void)n_in; (void)out_size;

    const int rowBlocks = (NN + 7) / 8;           // 8 rows (warps) per 256-thread block
    dim3 gemmGrid(256 / 64, (NN + 63) / 64);      // (4, 157)
    const int aggBlocks = 148 * 8;                // grid-stride over EE warps

    k_init<<<rowBlocks, 256>>>(x);

    // layer 1
    k_gemm<<<gemmGrid, 256>>>(W1);
    k_bias<<<1, 32>>>(b1);
    k_pre<<<rowBlocks, 256>>>();
    k_agg<<<aggBlocks, 256>>>(ew, esrc, edst);
    k_post<<<rowBlocks, 256>>>(out, 0);

    // layer 2
    k_gemm<<<gemmGrid, 256>>>(W2);
    k_bias<<<1, 32>>>(b2);
    k_pre<<<rowBlocks, 256>>>();
    k_agg<<<aggBlocks, 256>>>(ew, esrc, edst);
    k_post<<<rowBlocks, 256>>>(out, 1);
}